// round 1
// baseline (speedup 1.0000x reference)
#include <cuda_runtime.h>
#include <math.h>

#define T_DIM   512
#define B_DIM   2048
#define IN_DIMC 64
#define OBS_MID 28
#define OBS_BN  8
#define MSZ     16
#define NQ      6561   /* 3^8 */
#define NROWS   (T_DIM * B_DIM)

// ---- persistent device scratch (static allocation: allowed) ----
__device__ float g_GI[(NQ + 1) * 48];   // gi = xq @ W_ih^T + b_ih, per ternary obs code
__device__ float g_GH[(NQ + 1) * 48];   // gh = M[q] @ W_hh^T + b_hh, per bottleneck code (6561 = h0=0)
__device__ float g_M [(NQ + 1) * 16];   // m  = q2m(q)
__device__ float g_OUT[NQ * 16];        // out = tanh(M[q] @ act_w^T + act_b)
__device__ unsigned short g_qx[NROWS];  // obs-encoder ternary code per (t,b)

__device__ __forceinline__ float sigf(float x) {
    // XLA logistic lowering: 0.5 + 0.5*tanh(0.5*x)
    return 0.5f + 0.5f * tanhf(0.5f * x);
}
__device__ __forceinline__ int tern(float v) {
    float soft = 1.5f * tanhf(v) + 0.5f * tanhf(-3.0f * v);
    return (int)rintf(soft);   // {-1,0,1}, half-to-even like jnp.round
}

// ---------------------------------------------------------------------------
// Setup 1: M table (q2m chain) and OUT table (action head), one thread per code
// ---------------------------------------------------------------------------
__global__ void setup_m_out(
    const float* __restrict__ q2m_w0, const float* __restrict__ q2m_b0,
    const float* __restrict__ q2m_w1, const float* __restrict__ q2m_b1,
    const float* __restrict__ q2m_w2, const float* __restrict__ q2m_b2,
    const float* __restrict__ act_w,  const float* __restrict__ act_b)
{
    int e = blockIdx.x * blockDim.x + threadIdx.x;
    if (e > NQ) return;
    if (e == NQ) {                      // virtual zero-state entry
        #pragma unroll
        for (int k = 0; k < 16; k++) g_M[e * 16 + k] = 0.0f;
        return;
    }
    float q[8];
    int r = e;
    #pragma unroll
    for (int i = 0; i < 8; i++) { q[i] = (float)(r % 3 - 1); r /= 3; }

    float m0[16];
    #pragma unroll
    for (int j = 0; j < 16; j++) {
        float a = 0.0f;
        #pragma unroll
        for (int k = 0; k < 8; k++) a += q2m_w0[j * 8 + k] * q[k];
        m0[j] = tanhf(a + q2m_b0[j]);
    }
    float m1[16];
    #pragma unroll
    for (int j = 0; j < 16; j++) {
        float a = 0.0f;
        #pragma unroll
        for (int k = 0; k < 16; k++) a += q2m_w1[j * 16 + k] * m0[k];
        m1[j] = tanhf(a + q2m_b1[j]);
    }
    float m2[16];
    #pragma unroll
    for (int j = 0; j < 16; j++) {
        float a = 0.0f;
        #pragma unroll
        for (int k = 0; k < 16; k++) a += q2m_w2[j * 16 + k] * m1[k];
        m2[j] = tanhf(a + q2m_b2[j]);
        g_M[e * 16 + j] = m2[j];
    }
    #pragma unroll
    for (int j = 0; j < 16; j++) {
        float a = 0.0f;
        #pragma unroll
        for (int k = 0; k < 16; k++) a += act_w[j * 16 + k] * m2[k];
        g_OUT[e * 16 + j] = tanhf(a + act_b[j]);
    }
}

// ---------------------------------------------------------------------------
// Setup 2: GI (input gates from obs code) and GH (hidden gates from M table)
// ---------------------------------------------------------------------------
__global__ void setup_gi_gh(
    const float* __restrict__ wih, const float* __restrict__ whh,
    const float* __restrict__ bih, const float* __restrict__ bhh)
{
    int e = blockIdx.x * blockDim.x + threadIdx.x;
    if (e > NQ) return;

    float m[16];
    #pragma unroll
    for (int k = 0; k < 16; k++) m[k] = g_M[e * 16 + k];
    for (int g = 0; g < 48; g++) {
        float a = 0.0f;
        #pragma unroll
        for (int k = 0; k < 16; k++) a += m[k] * whh[g * 16 + k];
        g_GH[e * 48 + g] = a + bhh[g];
    }
    if (e < NQ) {
        float q[8];
        int r = e;
        #pragma unroll
        for (int i = 0; i < 8; i++) { q[i] = (float)(r % 3 - 1); r /= 3; }
        for (int g = 0; g < 48; g++) {
            float a = 0.0f;
            #pragma unroll
            for (int k = 0; k < 8; k++) a += q[k] * wih[g * 8 + k];
            g_GI[e * 48 + g] = a + bih[g];
        }
    }
}

// ---------------------------------------------------------------------------
// Obs encoder: 1M rows of 64 -> 28 (tanh) -> 28 (tanh) -> 8 (ternary) -> code
// One row per thread; transposed weights in smem, broadcast LDS.128 reads.
// ---------------------------------------------------------------------------
__global__ __launch_bounds__(256) void obs_kernel(
    const float* __restrict__ x,
    const float* __restrict__ w0, const float* __restrict__ b0,
    const float* __restrict__ w1, const float* __restrict__ b1,
    const float* __restrict__ w2, const float* __restrict__ b2)
{
    __shared__ __align__(16) float W0s[IN_DIMC * OBS_MID];   // [k][j]
    __shared__ __align__(16) float W1s[OBS_MID * OBS_MID];   // [k][j]
    __shared__ __align__(16) float W2s[OBS_MID * OBS_BN];    // [k][j]
    __shared__ float B0s[OBS_MID], B1s[OBS_MID], B2s[OBS_BN];

    int tid = threadIdx.x;
    for (int i = tid; i < IN_DIMC * OBS_MID; i += 256) {
        int k = i / OBS_MID, j = i % OBS_MID;
        W0s[i] = w0[j * IN_DIMC + k];
    }
    for (int i = tid; i < OBS_MID * OBS_MID; i += 256) {
        int k = i / OBS_MID, j = i % OBS_MID;
        W1s[i] = w1[j * OBS_MID + k];
    }
    for (int i = tid; i < OBS_MID * OBS_BN; i += 256) {
        int k = i / OBS_BN, j = i % OBS_BN;
        W2s[i] = w2[j * OBS_MID + k];
    }
    if (tid < OBS_MID) { B0s[tid] = b0[tid]; B1s[tid] = b1[tid]; }
    if (tid < OBS_BN)  { B2s[tid] = b2[tid]; }
    __syncthreads();

    int row = blockIdx.x * 256 + tid;          // grid is exact: 4096*256 = NROWS
    const float* xr = x + (size_t)row * IN_DIMC;

    float acc[OBS_MID];
    #pragma unroll
    for (int j = 0; j < OBS_MID; j++) acc[j] = 0.0f;

    #pragma unroll 4
    for (int k = 0; k < IN_DIMC; k++) {
        float xv = __ldg(&xr[k]);
        #pragma unroll
        for (int j4 = 0; j4 < 7; j4++) {
            float4 w = *reinterpret_cast<const float4*>(&W0s[k * OBS_MID + j4 * 4]);
            acc[j4 * 4 + 0] += xv * w.x;
            acc[j4 * 4 + 1] += xv * w.y;
            acc[j4 * 4 + 2] += xv * w.z;
            acc[j4 * 4 + 3] += xv * w.w;
        }
    }
    float h[OBS_MID];
    #pragma unroll
    for (int j = 0; j < OBS_MID; j++) h[j] = tanhf(acc[j] + B0s[j]);

    float a2[OBS_MID];
    #pragma unroll
    for (int j = 0; j < OBS_MID; j++) a2[j] = 0.0f;
    #pragma unroll
    for (int k = 0; k < OBS_MID; k++) {
        float xv = h[k];
        #pragma unroll
        for (int j4 = 0; j4 < 7; j4++) {
            float4 w = *reinterpret_cast<const float4*>(&W1s[k * OBS_MID + j4 * 4]);
            a2[j4 * 4 + 0] += xv * w.x;
            a2[j4 * 4 + 1] += xv * w.y;
            a2[j4 * 4 + 2] += xv * w.z;
            a2[j4 * 4 + 3] += xv * w.w;
        }
    }
    float h2[OBS_MID];
    #pragma unroll
    for (int j = 0; j < OBS_MID; j++) h2[j] = tanhf(a2[j] + B1s[j]);

    float a3[OBS_BN];
    #pragma unroll
    for (int j = 0; j < OBS_BN; j++) a3[j] = 0.0f;
    #pragma unroll
    for (int k = 0; k < OBS_MID; k++) {
        float xv = h2[k];
        #pragma unroll
        for (int j4 = 0; j4 < 2; j4++) {
            float4 w = *reinterpret_cast<const float4*>(&W2s[k * OBS_BN + j4 * 4]);
            a3[j4 * 4 + 0] += xv * w.x;
            a3[j4 * 4 + 1] += xv * w.y;
            a3[j4 * 4 + 2] += xv * w.z;
            a3[j4 * 4 + 3] += xv * w.w;
        }
    }
    int idx = 0, p = 1;
    #pragma unroll
    for (int j = 0; j < OBS_BN; j++) {
        idx += (tern(a3[j] + B2s[j]) + 1) * p;
        p *= 3;
    }
    g_qx[row] = (unsigned short)idx;
}

// ---------------------------------------------------------------------------
// Recurrent scan: 16 lanes per batch element, persistent over all T steps.
// State per element = bottleneck code (int). Gates come from GI/GH tables;
// only the m2q MLP (continuous in ht) is computed live.
// ---------------------------------------------------------------------------
__global__ __launch_bounds__(128) void recur_kernel(
    float* __restrict__ out,
    const float* __restrict__ m2q_w0, const float* __restrict__ m2q_b0,
    const float* __restrict__ m2q_w1, const float* __restrict__ m2q_b1,
    const float* __restrict__ m2q_w2, const float* __restrict__ m2q_b2)
{
    const int tid = threadIdx.x;
    const int j   = tid & 15;          // hidden-unit lane within group
    const int gb  = tid >> 4;          // group (element) within block, 0..7
    const int b   = blockIdx.x * 8 + gb;   // grid 256 -> b in [0,2048)

    __shared__ __align__(16) float s_ht[8][16];
    __shared__ __align__(16) float s_q1[8][16];
    __shared__ __align__(16) float s_q2[8][16];

    // per-lane weight rows in registers
    float w0r[16], w1r[16], w2r[16];
    #pragma unroll
    for (int k = 0; k < 16; k++) {
        w0r[k] = m2q_w0[j * 16 + k];
        w1r[k] = m2q_w1[j * 16 + k];
        w2r[k] = m2q_w2[(j & 7) * 16 + k];
    }
    const float b0r = m2q_b0[j];
    const float b1r = m2q_b1[j];
    const float b2r = m2q_b2[j & 7];

    int p3 = 1;
    for (int i = 0; i < (j & 7); i++) p3 *= 3;

    int qp = NQ;   // virtual zero-state code (h0 = 0)

    for (int t = 0; t < T_DIM; t++) {
        const int xq = (int)g_qx[t * B_DIM + b];
        const float* gi = g_GI + xq * 48;
        const float* gh = g_GH + qp * 48;
        const float  hv = g_M[qp * 16 + j];

        float r  = sigf(gi[j]      + gh[j]);
        float z  = sigf(gi[16 + j] + gh[16 + j]);
        float n  = tanhf(gi[32 + j] + r * gh[32 + j]);
        float ht = (1.0f - z) * n + z * hv;

        s_ht[gb][j] = ht;
        __syncwarp();

        // m2q layer 0: 16 x 16, dual accumulators for ILP
        float a0a = 0.0f, a0b = 0.0f;
        #pragma unroll
        for (int k4 = 0; k4 < 4; k4 += 2) {
            float4 v0 = reinterpret_cast<const float4*>(s_ht[gb])[k4];
            float4 v1 = reinterpret_cast<const float4*>(s_ht[gb])[k4 + 1];
            a0a += w0r[4 * k4 + 0] * v0.x; a0a += w0r[4 * k4 + 1] * v0.y;
            a0a += w0r[4 * k4 + 2] * v0.z; a0a += w0r[4 * k4 + 3] * v0.w;
            a0b += w0r[4 * k4 + 4] * v1.x; a0b += w0r[4 * k4 + 5] * v1.y;
            a0b += w0r[4 * k4 + 6] * v1.z; a0b += w0r[4 * k4 + 7] * v1.w;
        }
        float q1 = tanhf((a0a + a0b) + b0r);
        s_q1[gb][j] = q1;
        __syncwarp();

        // m2q layer 1: 16 x 16
        float a1a = 0.0f, a1b = 0.0f;
        #pragma unroll
        for (int k4 = 0; k4 < 4; k4 += 2) {
            float4 v0 = reinterpret_cast<const float4*>(s_q1[gb])[k4];
            float4 v1 = reinterpret_cast<const float4*>(s_q1[gb])[k4 + 1];
            a1a += w1r[4 * k4 + 0] * v0.x; a1a += w1r[4 * k4 + 1] * v0.y;
            a1a += w1r[4 * k4 + 2] * v0.z; a1a += w1r[4 * k4 + 3] * v0.w;
            a1b += w1r[4 * k4 + 4] * v1.x; a1b += w1r[4 * k4 + 5] * v1.y;
            a1b += w1r[4 * k4 + 6] * v1.z; a1b += w1r[4 * k4 + 7] * v1.w;
        }
        float q2v = tanhf((a1a + a1b) + b1r);
        s_q2[gb][j] = q2v;
        __syncwarp();

        // m2q layer 2: 8 x 16 (lanes 8..15 mirror lanes 0..7)
        float a2a = 0.0f, a2b = 0.0f;
        #pragma unroll
        for (int k4 = 0; k4 < 4; k4 += 2) {
            float4 v0 = reinterpret_cast<const float4*>(s_q2[gb])[k4];
            float4 v1 = reinterpret_cast<const float4*>(s_q2[gb])[k4 + 1];
            a2a += w2r[4 * k4 + 0] * v0.x; a2a += w2r[4 * k4 + 1] * v0.y;
            a2a += w2r[4 * k4 + 2] * v0.z; a2a += w2r[4 * k4 + 3] * v0.w;
            a2b += w2r[4 * k4 + 4] * v1.x; a2b += w2r[4 * k4 + 5] * v1.y;
            a2b += w2r[4 * k4 + 6] * v1.z; a2b += w2r[4 * k4 + 7] * v1.w;
        }
        float v = (a2a + a2b) + b2r;

        int c = (tern(v) + 1) * p3;
        c += __shfl_xor_sync(0xffffffffu, c, 1, 16);
        c += __shfl_xor_sync(0xffffffffu, c, 2, 16);
        c += __shfl_xor_sync(0xffffffffu, c, 4, 16);
        c += __shfl_xor_sync(0xffffffffu, c, 8, 16);
        int qn = c >> 1;   // 16-lane sum is exactly 2*code

        out[((size_t)(t * B_DIM + b)) * 16 + j] = g_OUT[qn * 16 + j];
        qp = qn;
    }
}

// ---------------------------------------------------------------------------
extern "C" void kernel_launch(void* const* d_in, const int* in_sizes, int n_in,
                              void* d_out, int out_size)
{
    (void)in_sizes; (void)n_in; (void)out_size;
    const float* x       = (const float*)d_in[0];
    const float* obs_w0  = (const float*)d_in[1];
    const float* obs_b0  = (const float*)d_in[2];
    const float* obs_w1  = (const float*)d_in[3];
    const float* obs_b1  = (const float*)d_in[4];
    const float* obs_w2  = (const float*)d_in[5];
    const float* obs_b2  = (const float*)d_in[6];
    const float* gru_wih = (const float*)d_in[7];
    const float* gru_whh = (const float*)d_in[8];
    const float* gru_bih = (const float*)d_in[9];
    const float* gru_bhh = (const float*)d_in[10];
    const float* m2q_w0  = (const float*)d_in[11];
    const float* m2q_b0  = (const float*)d_in[12];
    const float* m2q_w1  = (const float*)d_in[13];
    const float* m2q_b1  = (const float*)d_in[14];
    const float* m2q_w2  = (const float*)d_in[15];
    const float* m2q_b2  = (const float*)d_in[16];
    const float* q2m_w0  = (const float*)d_in[17];
    const float* q2m_b0  = (const float*)d_in[18];
    const float* q2m_w1  = (const float*)d_in[19];
    const float* q2m_b1  = (const float*)d_in[20];
    const float* q2m_w2  = (const float*)d_in[21];
    const float* q2m_b2  = (const float*)d_in[22];
    const float* act_w   = (const float*)d_in[23];
    const float* act_b   = (const float*)d_in[24];
    float* out = (float*)d_out;

    setup_m_out<<<26, 256>>>(q2m_w0, q2m_b0, q2m_w1, q2m_b1, q2m_w2, q2m_b2,
                             act_w, act_b);
    setup_gi_gh<<<26, 256>>>(gru_wih, gru_whh, gru_bih, gru_bhh);
    obs_kernel<<<NROWS / 256, 256>>>(x, obs_w0, obs_b0, obs_w1, obs_b1,
                                     obs_w2, obs_b2);
    recur_kernel<<<B_DIM / 8, 128>>>(out, m2q_w0, m2q_b0, m2q_w1, m2q_b1,
                                     m2q_w2, m2q_b2);
}

// round 2
// speedup vs baseline: 1.4658x; 1.4658x over previous
#include <cuda_runtime.h>
#include <math.h>

#define T_DIM   512
#define B_DIM   2048
#define IN_DIMC 64
#define OBS_MID 28
#define OBS_BN  8
#define NQ      6561   /* 3^8 */
#define NROWS   (T_DIM * B_DIM)

// ---- persistent device scratch ----
__device__ float4 g_GHM[(NQ + 1) * 16];   // (gh_r, gh_z, gh_n, m) per state, per lane
__device__ float4 g_GI4[NQ * 16];         // (gi_r, gi_z, gi_n, 0) per obs code, per lane
__device__ float  g_OUT[NQ * 16];         // tanh(M[q] @ act_w^T + act_b)
__device__ unsigned short g_qx[NROWS];    // obs ternary code per (t,b)
__device__ float  g_thr;                  // ternary decision threshold (fp-exact bisection)

__device__ __forceinline__ float sigf(float x) {
    return 0.5f + 0.5f * tanhf(0.5f * x);
}

// f32x2 packed-FMA helpers
__device__ __forceinline__ unsigned long long pack2(float a, float b) {
    unsigned long long r;
    asm("mov.b64 %0, {%1, %2};" : "=l"(r) : "f"(a), "f"(b));
    return r;
}
__device__ __forceinline__ void unpack2(unsigned long long v, float& a, float& b) {
    asm("mov.b64 {%0, %1}, %2;" : "=f"(a), "=f"(b) : "l"(v));
}
__device__ __forceinline__ void ffma2(unsigned long long& d, unsigned long long a,
                                      unsigned long long b) {
    asm("fma.rn.f32x2 %0, %1, %2, %0;" : "+l"(d) : "l"(a), "l"(b));
}

// ---------------------------------------------------------------------------
// Fused setup: threshold bisection + M/OUT/GHM/GI tables. One thread per code.
// ---------------------------------------------------------------------------
__global__ void setup_all(
    const float* __restrict__ q2m_w0, const float* __restrict__ q2m_b0,
    const float* __restrict__ q2m_w1, const float* __restrict__ q2m_b1,
    const float* __restrict__ q2m_w2, const float* __restrict__ q2m_b2,
    const float* __restrict__ act_w,  const float* __restrict__ act_b,
    const float* __restrict__ wih, const float* __restrict__ whh,
    const float* __restrict__ bih, const float* __restrict__ bhh)
{
    int e = blockIdx.x * blockDim.x + threadIdx.x;
    if (e == 0) {
        // bisection on the exact fp expression: soft(v) crosses 0.5
        float lo = 0.0f, hi = 2.0f;
        for (int it = 0; it < 80; it++) {
            float mid = 0.5f * (lo + hi);
            if (mid <= lo || mid >= hi) break;
            float s = 1.5f * tanhf(mid) + 0.5f * tanhf(-3.0f * mid);
            if (s > 0.5f) hi = mid; else lo = mid;
        }
        g_thr = lo;   // digit=1 iff v > lo  (rintf(0.5)==0 half-to-even)
    }
    if (e > NQ) return;

    float m2[16];
    float q[8];
    if (e == NQ) {
        #pragma unroll
        for (int k = 0; k < 16; k++) m2[k] = 0.0f;
    } else {
        int r = e;
        #pragma unroll
        for (int i = 0; i < 8; i++) { q[i] = (float)(r % 3 - 1); r /= 3; }
        float m0[16];
        #pragma unroll
        for (int jj = 0; jj < 16; jj++) {
            float a = 0.0f;
            #pragma unroll
            for (int k = 0; k < 8; k++) a += q2m_w0[jj * 8 + k] * q[k];
            m0[jj] = tanhf(a + q2m_b0[jj]);
        }
        float m1[16];
        #pragma unroll
        for (int jj = 0; jj < 16; jj++) {
            float a = 0.0f;
            #pragma unroll
            for (int k = 0; k < 16; k++) a += q2m_w1[jj * 16 + k] * m0[k];
            m1[jj] = tanhf(a + q2m_b1[jj]);
        }
        #pragma unroll
        for (int jj = 0; jj < 16; jj++) {
            float a = 0.0f;
            #pragma unroll
            for (int k = 0; k < 16; k++) a += q2m_w2[jj * 16 + k] * m1[k];
            m2[jj] = tanhf(a + q2m_b2[jj]);
        }
        // OUT table
        #pragma unroll
        for (int jj = 0; jj < 16; jj++) {
            float a = 0.0f;
            #pragma unroll
            for (int k = 0; k < 16; k++) a += act_w[jj * 16 + k] * m2[k];
            g_OUT[e * 16 + jj] = tanhf(a + act_b[jj]);
        }
    }
    // GHM table: (gh_r, gh_z, gh_n, m_j)
    #pragma unroll
    for (int jj = 0; jj < 16; jj++) {
        float ar = 0.0f, az = 0.0f, an = 0.0f;
        #pragma unroll
        for (int k = 0; k < 16; k++) {
            ar += m2[k] * whh[jj * 16 + k];
            az += m2[k] * whh[(16 + jj) * 16 + k];
            an += m2[k] * whh[(32 + jj) * 16 + k];
        }
        g_GHM[e * 16 + jj] = make_float4(ar + bhh[jj], az + bhh[16 + jj],
                                         an + bhh[32 + jj], m2[jj]);
    }
    // GI table
    if (e < NQ) {
        #pragma unroll
        for (int jj = 0; jj < 16; jj++) {
            float ar = 0.0f, az = 0.0f, an = 0.0f;
            #pragma unroll
            for (int k = 0; k < 8; k++) {
                ar += q[k] * wih[jj * 8 + k];
                az += q[k] * wih[(16 + jj) * 8 + k];
                an += q[k] * wih[(32 + jj) * 8 + k];
            }
            g_GI4[e * 16 + jj] = make_float4(ar + bih[jj], az + bih[16 + jj],
                                             an + bih[32 + jj], 0.0f);
        }
    }
}

// ---------------------------------------------------------------------------
// Obs encoder: one row per thread, f32x2 packed FMAs, threshold ternary.
// ---------------------------------------------------------------------------
__global__ __launch_bounds__(256) void obs_kernel(
    const float* __restrict__ x,
    const float* __restrict__ w0, const float* __restrict__ b0,
    const float* __restrict__ w1, const float* __restrict__ b1,
    const float* __restrict__ w2, const float* __restrict__ b2)
{
    __shared__ __align__(16) float W0s[IN_DIMC][OBS_MID];   // [k][j]
    __shared__ __align__(16) float W1s[OBS_MID][OBS_MID];
    __shared__ __align__(16) float W2s[OBS_MID][OBS_BN];
    __shared__ float B0s[OBS_MID], B1s[OBS_MID], B2s[OBS_BN];

    int tid = threadIdx.x;
    for (int i = tid; i < IN_DIMC * OBS_MID; i += 256) {
        int k = i / OBS_MID, jj = i % OBS_MID;
        W0s[k][jj] = w0[jj * IN_DIMC + k];
    }
    for (int i = tid; i < OBS_MID * OBS_MID; i += 256) {
        int k = i / OBS_MID, jj = i % OBS_MID;
        W1s[k][jj] = w1[jj * OBS_MID + k];
    }
    for (int i = tid; i < OBS_MID * OBS_BN; i += 256) {
        int k = i / OBS_BN, jj = i % OBS_BN;
        W2s[k][jj] = w2[jj * OBS_MID + k];
    }
    if (tid < OBS_MID) { B0s[tid] = b0[tid]; B1s[tid] = b1[tid]; }
    if (tid < OBS_BN)  { B2s[tid] = b2[tid]; }
    __syncthreads();

    const float thr = g_thr;
    int row = blockIdx.x * 256 + tid;
    const float4* xr4 = reinterpret_cast<const float4*>(x + (size_t)row * IN_DIMC);

    // ---- layer 0: 64 -> 28 ----
    unsigned long long acc[14];
    #pragma unroll
    for (int i = 0; i < 14; i++) acc[i] = 0ull;
    #pragma unroll 4
    for (int k4 = 0; k4 < 16; k4++) {
        float4 xv4 = __ldg(&xr4[k4]);
        float xs[4] = {xv4.x, xv4.y, xv4.z, xv4.w};
        #pragma unroll
        for (int kk = 0; kk < 4; kk++) {
            unsigned long long xv2 = pack2(xs[kk], xs[kk]);
            const ulonglong2* wrow =
                reinterpret_cast<const ulonglong2*>(&W0s[k4 * 4 + kk][0]);
            #pragma unroll
            for (int i = 0; i < 7; i++) {
                ulonglong2 w = wrow[i];
                ffma2(acc[2 * i],     xv2, w.x);
                ffma2(acc[2 * i + 1], xv2, w.y);
            }
        }
    }
    float h[OBS_MID];
    #pragma unroll
    for (int i = 0; i < 14; i++) unpack2(acc[i], h[2 * i], h[2 * i + 1]);
    #pragma unroll
    for (int jj = 0; jj < OBS_MID; jj++) h[jj] = tanhf(h[jj] + B0s[jj]);

    // ---- layer 1: 28 -> 28 ----
    unsigned long long a2[14];
    #pragma unroll
    for (int i = 0; i < 14; i++) a2[i] = 0ull;
    #pragma unroll
    for (int k = 0; k < OBS_MID; k++) {
        unsigned long long xv2 = pack2(h[k], h[k]);
        const ulonglong2* wrow = reinterpret_cast<const ulonglong2*>(&W1s[k][0]);
        #pragma unroll
        for (int i = 0; i < 7; i++) {
            ulonglong2 w = wrow[i];
            ffma2(a2[2 * i],     xv2, w.x);
            ffma2(a2[2 * i + 1], xv2, w.y);
        }
    }
    float h2[OBS_MID];
    #pragma unroll
    for (int i = 0; i < 14; i++) unpack2(a2[i], h2[2 * i], h2[2 * i + 1]);
    #pragma unroll
    for (int jj = 0; jj < OBS_MID; jj++) h2[jj] = tanhf(h2[jj] + B1s[jj]);

    // ---- layer 2: 28 -> 8, ternary via threshold ----
    unsigned long long a3[4];
    #pragma unroll
    for (int i = 0; i < 4; i++) a3[i] = 0ull;
    #pragma unroll
    for (int k = 0; k < OBS_MID; k++) {
        unsigned long long xv2 = pack2(h2[k], h2[k]);
        const ulonglong2* wrow = reinterpret_cast<const ulonglong2*>(&W2s[k][0]);
        ulonglong2 w0v = wrow[0];
        ulonglong2 w1v = wrow[1];
        ffma2(a3[0], xv2, w0v.x);
        ffma2(a3[1], xv2, w0v.y);
        ffma2(a3[2], xv2, w1v.x);
        ffma2(a3[3], xv2, w1v.y);
    }
    float v[OBS_BN];
    #pragma unroll
    for (int i = 0; i < 4; i++) unpack2(a3[i], v[2 * i], v[2 * i + 1]);

    int idx = 3280, p = 1;
    #pragma unroll
    for (int jj = 0; jj < OBS_BN; jj++) {
        float a = v[jj] + B2s[jj];
        int d = (a > thr) - (a < -thr);
        idx += d * p;
        p *= 3;
    }
    g_qx[row] = (unsigned short)idx;
}

// ---------------------------------------------------------------------------
// Recurrent scan: 16 lanes per batch element. Critical path per step:
// LDG.128 GHM[qp] -> gates (2-deep tanh) -> 3x smem-exchanged 16-dots ->
// threshold compare -> 2 ballots + LUT -> qn.
// ---------------------------------------------------------------------------
__global__ __launch_bounds__(128) void recur_kernel(
    float* __restrict__ out,
    const float* __restrict__ m2q_w0, const float* __restrict__ m2q_b0,
    const float* __restrict__ m2q_w1, const float* __restrict__ m2q_b1,
    const float* __restrict__ m2q_w2, const float* __restrict__ m2q_b2)
{
    __shared__ int s_P[256];
    __shared__ __align__(16) float s_ht[8][16];
    __shared__ __align__(16) float s_q1[8][16];
    __shared__ __align__(16) float s_q2[8][16];

    const int tid = threadIdx.x;
    for (int i = tid; i < 256; i += 128) {
        int s = 0, p = 1;
        #pragma unroll
        for (int bi = 0; bi < 8; bi++) { s += ((i >> bi) & 1) * p; p *= 3; }
        s_P[i] = s;
    }

    const int j  = tid & 15;
    const int gb = tid >> 4;
    const int b  = blockIdx.x * 8 + gb;

    float w0r[16], w1r[16], w2r[16];
    #pragma unroll
    for (int k = 0; k < 16; k++) {
        w0r[k] = m2q_w0[j * 16 + k];
        w1r[k] = m2q_w1[j * 16 + k];
        w2r[k] = m2q_w2[(j & 7) * 16 + k];
    }
    const float b0r = m2q_b0[j];
    const float b1r = m2q_b1[j];
    const float b2r = m2q_b2[j & 7];
    const float thr = g_thr;
    __syncthreads();

    int qp = NQ;
    int xq = (int)g_qx[b];
    float4 gi = g_GI4[xq * 16 + j];

    for (int t = 0; t < T_DIM; t++) {
        float4 ghm = g_GHM[qp * 16 + j];         // critical L2/L1 load

        // prefetch next-step gi (independent of the recurrence)
        int tn = (t + 1 < T_DIM) ? (t + 1) * B_DIM + b : b;
        int xqn = (int)g_qx[tn];
        float4 gin = g_GI4[xqn * 16 + j];

        float r  = sigf(gi.x + ghm.x);
        float z  = sigf(gi.y + ghm.y);
        float n  = tanhf(gi.z + r * ghm.z);
        float ht = (1.0f - z) * n + z * ghm.w;

        s_ht[gb][j] = ht;
        __syncwarp();

        float a0a = 0.0f, a0b = 0.0f;
        #pragma unroll
        for (int k4 = 0; k4 < 4; k4 += 2) {
            float4 v0 = reinterpret_cast<const float4*>(s_ht[gb])[k4];
            float4 v1 = reinterpret_cast<const float4*>(s_ht[gb])[k4 + 1];
            a0a += w0r[4 * k4 + 0] * v0.x; a0a += w0r[4 * k4 + 1] * v0.y;
            a0a += w0r[4 * k4 + 2] * v0.z; a0a += w0r[4 * k4 + 3] * v0.w;
            a0b += w0r[4 * k4 + 4] * v1.x; a0b += w0r[4 * k4 + 5] * v1.y;
            a0b += w0r[4 * k4 + 6] * v1.z; a0b += w0r[4 * k4 + 7] * v1.w;
        }
        float q1 = tanhf((a0a + a0b) + b0r);
        s_q1[gb][j] = q1;
        __syncwarp();

        float a1a = 0.0f, a1b = 0.0f;
        #pragma unroll
        for (int k4 = 0; k4 < 4; k4 += 2) {
            float4 v0 = reinterpret_cast<const float4*>(s_q1[gb])[k4];
            float4 v1 = reinterpret_cast<const float4*>(s_q1[gb])[k4 + 1];
            a1a += w1r[4 * k4 + 0] * v0.x; a1a += w1r[4 * k4 + 1] * v0.y;
            a1a += w1r[4 * k4 + 2] * v0.z; a1a += w1r[4 * k4 + 3] * v0.w;
            a1b += w1r[4 * k4 + 4] * v1.x; a1b += w1r[4 * k4 + 5] * v1.y;
            a1b += w1r[4 * k4 + 6] * v1.z; a1b += w1r[4 * k4 + 7] * v1.w;
        }
        float q2v = tanhf((a1a + a1b) + b1r);
        s_q2[gb][j] = q2v;
        __syncwarp();

        float a2a = 0.0f, a2b = 0.0f;
        #pragma unroll
        for (int k4 = 0; k4 < 4; k4 += 2) {
            float4 v0 = reinterpret_cast<const float4*>(s_q2[gb])[k4];
            float4 v1 = reinterpret_cast<const float4*>(s_q2[gb])[k4 + 1];
            a2a += w2r[4 * k4 + 0] * v0.x; a2a += w2r[4 * k4 + 1] * v0.y;
            a2a += w2r[4 * k4 + 2] * v0.z; a2a += w2r[4 * k4 + 3] * v0.w;
            a2b += w2r[4 * k4 + 4] * v1.x; a2b += w2r[4 * k4 + 5] * v1.y;
            a2b += w2r[4 * k4 + 6] * v1.z; a2b += w2r[4 * k4 + 7] * v1.w;
        }
        float v = (a2a + a2b) + b2r;

        unsigned B1 = __ballot_sync(0xffffffffu, v > thr);
        unsigned Bm = __ballot_sync(0xffffffffu, v < -thr);
        int base = tid & 16;
        int qn = 3280 + s_P[(B1 >> base) & 0xFF] - s_P[(Bm >> base) & 0xFF];

        out[((size_t)(t * B_DIM + b)) * 16 + j] = g_OUT[qn * 16 + j];
        qp = qn;
        gi = gin;
    }
}

// ---------------------------------------------------------------------------
extern "C" void kernel_launch(void* const* d_in, const int* in_sizes, int n_in,
                              void* d_out, int out_size)
{
    (void)in_sizes; (void)n_in; (void)out_size;
    const float* x       = (const float*)d_in[0];
    const float* obs_w0  = (const float*)d_in[1];
    const float* obs_b0  = (const float*)d_in[2];
    const float* obs_w1  = (const float*)d_in[3];
    const float* obs_b1  = (const float*)d_in[4];
    const float* obs_w2  = (const float*)d_in[5];
    const float* obs_b2  = (const float*)d_in[6];
    const float* gru_wih = (const float*)d_in[7];
    const float* gru_whh = (const float*)d_in[8];
    const float* gru_bih = (const float*)d_in[9];
    const float* gru_bhh = (const float*)d_in[10];
    const float* m2q_w0  = (const float*)d_in[11];
    const float* m2q_b0  = (const float*)d_in[12];
    const float* m2q_w1  = (const float*)d_in[13];
    const float* m2q_b1  = (const float*)d_in[14];
    const float* m2q_w2  = (const float*)d_in[15];
    const float* m2q_b2  = (const float*)d_in[16];
    const float* q2m_w0  = (const float*)d_in[17];
    const float* q2m_b0  = (const float*)d_in[18];
    const float* q2m_w1  = (const float*)d_in[19];
    const float* q2m_b1  = (const float*)d_in[20];
    const float* q2m_w2  = (const float*)d_in[21];
    const float* q2m_b2  = (const float*)d_in[22];
    const float* act_w   = (const float*)d_in[23];
    const float* act_b   = (const float*)d_in[24];
    float* out = (float*)d_out;

    setup_all<<<26, 256>>>(q2m_w0, q2m_b0, q2m_w1, q2m_b1, q2m_w2, q2m_b2,
                           act_w, act_b, gru_wih, gru_whh, gru_bih, gru_bhh);
    obs_kernel<<<NROWS / 256, 256>>>(x, obs_w0, obs_b0, obs_w1, obs_b1,
                                     obs_w2, obs_b2);
    recur_kernel<<<B_DIM / 8, 128>>>(out, m2q_w0, m2q_b0, m2q_w1, m2q_b1,
                                     m2q_w2, m2q_b2);
}